// round 8
// baseline (speedup 1.0000x reference)
#include <cuda_runtime.h>
#include <cuda_bf16.h>
#include <math.h>
#include <stdint.h>

// Problem constants (MinGRUCell: B=8, T=4096, D=256, H=256)
#define BB 8
#define TT 4096
#define DD 256
#define HH 256
#define MM (BB * TT)          // 32768 rows
#define NN 512                // logical N: gate(256) + update(256)

// Chunked scan config: chunk length 32 == warp size (epilogue scan unit)
#define NCH 128
#define CLEN 32               // NCH*CLEN == TT

// tcgen05 only exists in the arch-specific compilation pass.
#if defined(__CUDA_ARCH_FEAT_SM103_ALL) || defined(__CUDA_ARCH_FEAT_SM100_ALL) || defined(__CUDA_ARCH_FEAT_SM101_ALL)
#define HAS_TCGEN05 1
#else
#define HAS_TCGEN05 0
#endif

// Scratch: per-timestep inclusive chunk prefixes (A_p, B_p), layout [M, H]
__device__ float Ap_scratch[(size_t)MM * HH];
__device__ float Bp_scratch[(size_t)MM * HH];
__device__ float chunkA[(size_t)BB * NCH * HH];
__device__ float chunkB[(size_t)BB * NCH * HH];
__device__ float hstart[(size_t)BB * NCH * HH];
// Pre-split weights: rows 0..255 = Wz, 256..511 = Wh   [NN, DD] bf16
__device__ __nv_bfloat16 Wcat_hi[(size_t)NN * DD];
__device__ __nv_bfloat16 Wcat_lo[(size_t)NN * DD];
// Pre-split activations [MM, DD] bf16
__device__ __nv_bfloat16 x_hi[(size_t)MM * DD];
__device__ __nv_bfloat16 x_lo[(size_t)MM * DD];

// ---------------------------------------------------------------------------
// PTX helpers
// ---------------------------------------------------------------------------
__device__ __forceinline__ uint32_t smem_u32(const void* p) {
    uint32_t a;
    asm("{ .reg .u64 t; cvta.to.shared.u64 t, %1; cvt.u32.u64 %0, t; }"
        : "=r"(a) : "l"(p));
    return a;
}

#define SW128(o) ((o) ^ (((o) >> 3) & 0x70))

static constexpr uint64_t SMEM_DESC_BASE_SW128_C =
    (uint64_t(2)  << 61) | (uint64_t(1) << 46) | (uint64_t(64) << 32) | (uint64_t(1) << 16);
#define MK_DESC(addr) (SMEM_DESC_BASE_SW128_C | ((uint64_t)((addr) >> 4) & 0x3FFF))

#define CP_ASYNC16(dst, src) \
    asm volatile("cp.async.cg.shared.global [%0], [%1], 16;" :: "r"(dst), "l"(src) : "memory")
#define CP_COMMIT()  asm volatile("cp.async.commit_group;" ::: "memory")
#define CP_WAIT1()   asm volatile("cp.async.wait_group 1;" ::: "memory")
#define CP_WAIT0()   asm volatile("cp.async.wait_group 0;" ::: "memory")

#if HAS_TCGEN05
#define TC_ALLOC(sm, n)  asm volatile("tcgen05.alloc.cta_group::1.sync.aligned.shared::cta.b32 [%0], %1;" :: "r"((uint32_t)(sm)), "r"((uint32_t)(n)) : "memory")
#define TC_DEALLOC(t, n) asm volatile("tcgen05.dealloc.cta_group::1.sync.aligned.b32 %0, %1;" :: "r"(t), "r"((uint32_t)(n)))
#define TC_RELINQ()      asm volatile("tcgen05.relinquish_alloc_permit.cta_group::1.sync.aligned;")
#define TC_COMMIT(mb)    asm volatile("tcgen05.commit.cta_group::1.mbarrier::arrive::one.shared::cluster.b64 [%0];" :: "r"((uint32_t)(mb)) : "memory")
#define TC_WAIT_LD()     asm volatile("tcgen05.wait::ld.sync.aligned;" ::: "memory")
#define TC_FENCE_AFTER() asm volatile("tcgen05.fence::after_thread_sync;" ::: "memory")
#define FENCE_ASYNC()    asm volatile("fence.proxy.async.shared::cta;" ::: "memory")
#define MBAR_INIT(mb, c) asm volatile("mbarrier.init.shared.b64 [%0], %1;" :: "r"((uint32_t)(mb)), "r"((uint32_t)(c)) : "memory")

#define MBAR_WAIT(mb, ph) do {                                                 \
    uint32_t _m = (uint32_t)(mb), _p = (uint32_t)(ph), _d;                     \
    asm volatile("{\n\t.reg .pred p;\n\t"                                      \
        "mbarrier.try_wait.parity.acquire.cta.shared::cta.b64 p, [%1], %2;\n\t"\
        "selp.b32 %0, 1, 0, p;\n\t}"                                           \
        : "=r"(_d) : "r"(_m), "r"(_p) : "memory");                             \
    if (!_d) {                                                                 \
        asm volatile("{\n\t.reg .pred P1;\n\t"                                 \
            "WL_%=:\n\t"                                                       \
            "mbarrier.try_wait.parity.acquire.cta.shared::cta.b64 P1, [%0], %1, 0x989680;\n\t" \
            "@P1 bra.uni WD_%=;\n\t"                                           \
            "bra.uni WL_%=;\n\t"                                               \
            "WD_%=:\n\t}"                                                      \
            :: "r"(_m), "r"(_p) : "memory");                                   \
    }                                                                          \
} while (0)

#define LDTM32(r, ta)                                                          \
    asm volatile("tcgen05.ld.sync.aligned.32x32b.x32.b32 "                     \
        "{%0,%1,%2,%3,%4,%5,%6,%7,%8,%9,%10,%11,%12,%13,%14,%15,"              \
        "%16,%17,%18,%19,%20,%21,%22,%23,%24,%25,%26,%27,%28,%29,%30,%31}, [%32];" \
        : "=r"((r)[0]),"=r"((r)[1]),"=r"((r)[2]),"=r"((r)[3]),                 \
          "=r"((r)[4]),"=r"((r)[5]),"=r"((r)[6]),"=r"((r)[7]),                 \
          "=r"((r)[8]),"=r"((r)[9]),"=r"((r)[10]),"=r"((r)[11]),               \
          "=r"((r)[12]),"=r"((r)[13]),"=r"((r)[14]),"=r"((r)[15]),             \
          "=r"((r)[16]),"=r"((r)[17]),"=r"((r)[18]),"=r"((r)[19]),             \
          "=r"((r)[20]),"=r"((r)[21]),"=r"((r)[22]),"=r"((r)[23]),             \
          "=r"((r)[24]),"=r"((r)[25]),"=r"((r)[26]),"=r"((r)[27]),             \
          "=r"((r)[28]),"=r"((r)[29]),"=r"((r)[30]),"=r"((r)[31])              \
        : "r"(ta))

__device__ __forceinline__ void mma_f16_ss(uint32_t d, uint64_t a, uint64_t b,
                                           uint32_t idesc, uint32_t en) {
    asm volatile(
        "{\n\t.reg .pred p;\n\tsetp.ne.u32 p, %5, 0;\n\t"
        "tcgen05.mma.cta_group::1.kind::f16 [%0], %1, %2, %3, {%4, %4, %4, %4}, p;\n\t}"
        :: "r"(d), "l"(a), "l"(b), "r"(idesc), "r"(0u), "r"(en) : "memory");
}
#endif // HAS_TCGEN05

// idesc: dtype=F32, atype=BF16, btype=BF16, N=256, M=128
static constexpr uint32_t GEMM_IDESC =
    (1u << 4) | (1u << 7) | (1u << 10) | ((256u / 8) << 17) | ((128u / 16) << 24);

// ---------------------------------------------------------------------------
// Weight pre-split
// ---------------------------------------------------------------------------
__global__ __launch_bounds__(256)
void mingru_wprep_kernel(const float* __restrict__ Wz, const float* __restrict__ Wh)
{
    const int i = blockIdx.x * 256 + threadIdx.x;
    const int n = i >> 8;
    const int d = i & 255;
    float v = (n < HH) ? Wz[n * DD + d] : Wh[(n - HH) * DD + d];
    __nv_bfloat16 hi = __float2bfloat16(v);
    Wcat_hi[i] = hi;
    Wcat_lo[i] = __float2bfloat16(v - __bfloat162float(hi));
}

// ---------------------------------------------------------------------------
// Activation pre-split: x fp32 -> x_hi, x_lo bf16 (one float4 per thread)
// ---------------------------------------------------------------------------
__global__ __launch_bounds__(256)
void mingru_xsplit_kernel(const float* __restrict__ x)
{
    const size_t i4 = (size_t)blockIdx.x * 256 + threadIdx.x;
    float4 v = reinterpret_cast<const float4*>(x)[i4];
    __nv_bfloat16 h0 = __float2bfloat16(v.x);
    __nv_bfloat16 h1 = __float2bfloat16(v.y);
    __nv_bfloat16 h2 = __float2bfloat16(v.z);
    __nv_bfloat16 h3 = __float2bfloat16(v.w);
    __nv_bfloat162 hp0(h0, h1), hp1(h2, h3);
    __nv_bfloat162 lp0(__float2bfloat16(v.x - __bfloat162float(h0)),
                       __float2bfloat16(v.y - __bfloat162float(h1)));
    __nv_bfloat162 lp1(__float2bfloat16(v.z - __bfloat162float(h2)),
                       __float2bfloat16(v.w - __bfloat162float(h3)));
    uint2 hw = make_uint2(*(uint32_t*)&hp0, *(uint32_t*)&hp1);
    uint2 lw = make_uint2(*(uint32_t*)&lp0, *(uint32_t*)&lp1);
    reinterpret_cast<uint2*>(x_hi)[i4] = hw;
    reinterpret_cast<uint2*>(x_lo)[i4] = lw;
}

// ---------------------------------------------------------------------------
// Fused tcgen05 GEMM: per CTA M=128 rows, BOTH gate (TMEM cols 0..255) and
// update (cols 256..511). 8 pipeline steps (kc, half); 2 stage buffers.
// Buffer-reuse guard: load(s+2) waits for commit of MMA step s (same buffer).
// Epilogue: bias+sigmoid, per-warp affine scan over 32 lanes (= one chunk),
// stores per-timestep prefixes (Ap,Bp) and chunk summaries. grid=256, 256 thr.
// ---------------------------------------------------------------------------
#define KCH 64
#define NSTEPS 8
// header: [0..4) tmem ptr, [8..16) mbar, [1024..2048) bz, [2048..3072) bh
#define HDR_BZ 1024
#define HDR_BH 2048
#define STAGE0_OFF 4096
#define STAGE_BYTES (96 * 1024)
#define ST_A_HI 0
#define ST_A_LO (16 * 1024)
#define ST_B_HI (32 * 1024)
#define ST_B_LO (64 * 1024)
#define GEMM_SMEM (STAGE0_OFF + 2 * STAGE_BYTES)

__global__ __launch_bounds__(256, 1)
void mingru_gemm_tc(const float* __restrict__ bz,
                    const float* __restrict__ bh)
{
#if HAS_TCGEN05
    extern __shared__ char smem_raw[];
    char* smem = (char*)(((uintptr_t)smem_raw + 1023) & ~(uintptr_t)1023);
    const uint32_t sbase = smem_u32(smem);

    const int tid = threadIdx.x;            // 0..255
    const int m0 = blockIdx.x * 128;

    if (tid < 32) TC_ALLOC(sbase + 0, 512);
    if (tid == 0) MBAR_INIT(sbase + 8, 1);
    *reinterpret_cast<float*>(smem + HDR_BZ + tid * 4) = bz[tid];
    *reinterpret_cast<float*>(smem + HDR_BH + tid * 4) = bh[tid];
    __syncthreads();
    uint32_t tmem;
    asm volatile("ld.shared.b32 %0, [%1];" : "=r"(tmem) : "r"(sbase + 0));

    // ---- stage loader: step s -> buffer s&1, kc=s>>1, half nh=s&1 ----
    auto load_step = [&](int s) {
        const int kc = s >> 1;
        const int nh = s & 1;
        const uint32_t st = sbase + STAGE0_OFF + (s & 1) * STAGE_BYTES;
        const int k0 = kc * KCH;
        // A_hi + A_lo: 128 rows x 8 x 16B each
#pragma unroll
        for (int j = 0; j < 4; j++) {
            const int i = j * 256 + tid;         // 0..1023
            const int row = i >> 3;
            const int c16 = i & 7;
            const uint32_t off = SW128((uint32_t)(row * 128 + c16 * 16));
            const size_t src = (size_t)(m0 + row) * DD + k0 + c16 * 8;
            CP_ASYNC16(st + ST_A_HI + off, (const char*)&x_hi[src]);
            CP_ASYNC16(st + ST_A_LO + off, (const char*)&x_lo[src]);
        }
        // B_hi + B_lo: 256 rows (half nh of Wcat) x 8 x 16B each
#pragma unroll
        for (int j = 0; j < 8; j++) {
            const int i = j * 256 + tid;         // 0..2047
            const int row = i >> 3;
            const int c16 = i & 7;
            const uint32_t off = SW128((uint32_t)(row * 128 + c16 * 16));
            const size_t src = (size_t)(nh * 256 + row) * DD + k0 + c16 * 8;
            CP_ASYNC16(st + ST_B_HI + off, (const char*)&Wcat_hi[src]);
            CP_ASYNC16(st + ST_B_LO + off, (const char*)&Wcat_lo[src]);
        }
        CP_COMMIT();
    };

    load_step(0);
    load_step(1);

    for (int s = 0; s < NSTEPS; s++) {
        if (s < NSTEPS - 1) { CP_WAIT1(); } else { CP_WAIT0(); }
        __syncthreads();

        if (tid == 0) {
            FENCE_ASYNC();
            const int kc = s >> 1;
            const int nh = s & 1;
            const uint32_t st = sbase + STAGE0_OFF + (s & 1) * STAGE_BYTES;
            const uint64_t ahi = MK_DESC(st + ST_A_HI);
            const uint64_t alo = MK_DESC(st + ST_A_LO);
            const uint64_t bhi = MK_DESC(st + ST_B_HI);
            const uint64_t blo = MK_DESC(st + ST_B_LO);
            const uint64_t ad[3] = { ahi, alo, ahi };
            const uint64_t bd[3] = { bhi, bhi, blo };
            const uint32_t dreg = tmem + nh * 256;
#pragma unroll
            for (int p = 0; p < 3; p++)
#pragma unroll
                for (int ks = 0; ks < 4; ks++)
                    mma_f16_ss(dreg, ad[p] + ks * 2, bd[p] + ks * 2,
                               GEMM_IDESC, (kc > 0 || p > 0 || ks > 0) ? 1u : 0u);
            TC_COMMIT(sbase + 8);
        }
        // Wait for MMA step s completion: buffer s&1 (the one load(s+2)
        // targets) is now free. MMA s has been running since issue above;
        // load(s+2) still overlaps MMA(s+1) in the next iteration.
        MBAR_WAIT(sbase + 8, s & 1);
        if (s + 2 < NSTEPS) load_step(s + 2);
    }
    TC_FENCE_AFTER();

    // ---- Epilogue: warp w -> rows (w&3)*32+lane (t = lane within chunk),
    //      cols (w>>2)*128..+128 in 4 blocks of 32. Affine scan per column. ----
    {
        const int w = tid >> 5;
        const int lane = tid & 31;
        const int row = (w & 3) * 32 + lane;
        const int gm = m0 + row;
        const int b = gm >> 12;                   // / TT
        const int t = gm & (TT - 1);
        const int c = t >> 5;                     // chunk index (CLEN=32)
        const int cb0 = (w >> 2) * 128;
        const float* __restrict__ bz_s = reinterpret_cast<const float*>(smem + HDR_BZ);
        const float* __restrict__ bh_s = reinterpret_cast<const float*>(smem + HDR_BH);
        float* __restrict__ aprow = Ap_scratch + (size_t)gm * HH;
        float* __restrict__ bprow = Bp_scratch + (size_t)gm * HH;

#pragma unroll
        for (int q = 0; q < 4; q++) {
            const int j0 = cb0 + q * 32;
            uint32_t rg[32], ru[32];
            LDTM32(rg, tmem + j0);
            LDTM32(ru, tmem + 256 + j0);
            TC_WAIT_LD();
            float ap[32], bp[32];
#pragma unroll
            for (int j = 0; j < 32; j++) {
                float zg = __uint_as_float(rg[j]) + bz_s[j0 + j];
                float g = 1.0f / (1.0f + __expf(-zg));
                float u = __uint_as_float(ru[j]) + bh_s[j0 + j];
                float A = 1.0f - g;
                float Bv = g * u;
                // inclusive affine scan over lanes (t order)
#pragma unroll
                for (int d = 1; d < 32; d <<= 1) {
                    float Ad = __shfl_up_sync(0xffffffffu, A, d);
                    float Bd = __shfl_up_sync(0xffffffffu, Bv, d);
                    if (lane >= d) { Bv = fmaf(A, Bd, Bv); A *= Ad; }
                }
                ap[j] = A; bp[j] = Bv;
            }
            // store per-timestep prefixes (vectorized)
#pragma unroll
            for (int v = 0; v < 8; v++) {
                float4 va = make_float4(ap[v*4+0], ap[v*4+1], ap[v*4+2], ap[v*4+3]);
                float4 vb = make_float4(bp[v*4+0], bp[v*4+1], bp[v*4+2], bp[v*4+3]);
                *reinterpret_cast<float4*>(&aprow[j0 + v * 4]) = va;
                *reinterpret_cast<float4*>(&bprow[j0 + v * 4]) = vb;
            }
            // chunk summary = inclusive prefix at last timestep (lane 31)
            if (lane == 31) {
                const size_t ci = ((size_t)b * NCH + c) * HH + j0;
#pragma unroll
                for (int j = 0; j < 32; j++) {
                    chunkA[ci + j] = ap[j];
                    chunkB[ci + j] = bp[j];
                }
            }
        }
    }

    __syncthreads();
    if (tid < 32) {
        TC_RELINQ();
        TC_DEALLOC(tmem, 512);
    }
#endif // HAS_TCGEN05
}

// ---------------------------------------------------------------------------
// Scan pass 2: carry h0 across chunk summaries with 8-wide load batching.
// ---------------------------------------------------------------------------
__global__ __launch_bounds__(256)
void mingru_scan_pass2(const float* __restrict__ h0)
{
    const int idx = blockIdx.x * blockDim.x + threadIdx.x;  // 0..2047
    const int h = idx & (HH - 1);
    const int b = idx >> 8;

    float hc = h0[b * HH + h];
    const size_t cb0 = (size_t)b * NCH * HH + h;
    for (int c0 = 0; c0 < NCH; c0 += 8) {
        float a[8], bb[8];
#pragma unroll
        for (int j = 0; j < 8; j++) {
            const size_t ci = cb0 + (size_t)(c0 + j) * HH;
            a[j]  = chunkA[ci];
            bb[j] = chunkB[ci];
        }
#pragma unroll
        for (int j = 0; j < 8; j++) {
            const size_t ci = cb0 + (size_t)(c0 + j) * HH;
            hstart[ci] = hc;
            hc = fmaf(a[j], hc, bb[j]);
        }
    }
}

// ---------------------------------------------------------------------------
// Scan pass 3 (elementwise): out_t = Ap_t * hstart(chunk) + Bp_t.
// No carried dependency — pure bandwidth.
// ---------------------------------------------------------------------------
__global__ __launch_bounds__(256)
void mingru_scan_pass3(float* __restrict__ out)
{
    const int idx = blockIdx.x * blockDim.x + threadIdx.x;
    const int h = idx & (HH - 1);
    const int c = (idx >> 8) & (NCH - 1);
    const int b = idx >> 15;

    const size_t base = ((size_t)b * TT + (size_t)c * CLEN) * HH + h;
    const float* __restrict__ app = Ap_scratch + base;
    const float* __restrict__ bpp = Bp_scratch + base;
    float* __restrict__ op = out + base;

    const float hs = hstart[idx];
#pragma unroll 8
    for (int t = 0; t < CLEN; t++) {
        const size_t off = (size_t)t * HH;
        op[off] = fmaf(app[off], hs, bpp[off]);
    }
}

extern "C" void kernel_launch(void* const* d_in, const int* in_sizes, int n_in,
                              void* d_out, int out_size)
{
    const float* x  = (const float*)d_in[0];   // [B,T,D]
    const float* h0 = (const float*)d_in[1];   // [B,H]
    const float* Wz = (const float*)d_in[2];   // [H,D]
    const float* bz = (const float*)d_in[3];   // [H]
    const float* Wh = (const float*)d_in[4];   // [H,D]
    const float* bh = (const float*)d_in[5];   // [H]
    float* out = (float*)d_out;                // [B,T,H]

    cudaFuncSetAttribute(mingru_gemm_tc,
                         cudaFuncAttributeMaxDynamicSharedMemorySize, GEMM_SMEM);

    mingru_wprep_kernel<<<NN * DD / 256, 256>>>(Wz, Wh);
    mingru_xsplit_kernel<<<MM * DD / 4 / 256, 256>>>(x);

    mingru_gemm_tc<<<MM / 128, 256, GEMM_SMEM>>>(bz, bh);

    mingru_scan_pass2<<<BB * HH / 256, 256>>>(h0);
    mingru_scan_pass3<<<BB * NCH * HH / 256, 256>>>(out);
}